// round 1
// baseline (speedup 1.0000x reference)
#include <cuda_runtime.h>
#include <cstdint>

// Scratch: Q,K,V in per-(window,head) layout [bw][h][t][d], 512*8*64*64 floats each (64MB).
__device__ float g_q[512 * 8 * 64 * 64];
__device__ float g_k[512 * 8 * 64 * 64];
__device__ float g_v[512 * 8 * 64 * 64];

__device__ __forceinline__ uint32_t f2tf(float f) {
    uint32_t u;
    asm("cvt.rna.tf32.f32 %0, %1;" : "=r"(u) : "f"(f));
    return u;
}

__device__ __forceinline__ void mma_tf32(float c[4], const uint32_t a[4], const uint32_t b[2]) {
    asm volatile(
        "mma.sync.aligned.m16n8k8.row.col.f32.tf32.tf32.f32 "
        "{%0,%1,%2,%3}, {%4,%5,%6,%7}, {%8,%9}, {%0,%1,%2,%3};"
        : "+f"(c[0]), "+f"(c[1]), "+f"(c[2]), "+f"(c[3])
        : "r"(a[0]), "r"(a[1]), "r"(a[2]), "r"(a[3]), "r"(b[0]), "r"(b[1]));
}

// ---------------------------------------------------------------------------
// Kernel A: QKV projection. y[m, n] = sum_k x[m,k] * W[n,k] + b[n]
// M = 32768 tokens, N = 1536 (Q|K|V concat), K = 512. CTA tile 128x128x32.
// Epilogue scatters into g_q/g_k/g_v as [bw][h][t][d].
// ---------------------------------------------------------------------------
__global__ void __launch_bounds__(256, 1) qkv_proj_kernel(
    const float* __restrict__ x,
    const float* __restrict__ Wq, const float* __restrict__ bq,
    const float* __restrict__ Wk, const float* __restrict__ bk,
    const float* __restrict__ Wv, const float* __restrict__ bv)
{
    __shared__ uint32_t As[128][36];  // [m][k], pitch 36 (mod32=4) -> conflict-free frags
    __shared__ uint32_t Bs[128][36];  // [n][k]

    const int tid  = threadIdx.x;
    const int warp = tid >> 5, lane = tid & 31;
    const int g = lane >> 2, tig = lane & 3;
    const int wm = (warp >> 1) * 32;  // warp row offset within CTA tile
    const int wn = (warp & 1) * 64;   // warp col offset

    const int mb = blockIdx.x * 128;
    const int nb = blockIdx.y * 128;
    const int which = nb >> 9;            // 0=Q, 1=K, 2=V (tile never crosses boundary)
    const int nw0 = nb & 511;             // col within the selected weight matrix
    const float* __restrict__ W    = (which == 0) ? Wq : (which == 1) ? Wk : Wv;
    const float* __restrict__ bias = (which == 0) ? bq : (which == 1) ? bk : bv;
    float* __restrict__ dst        = (which == 0) ? g_q : (which == 1) ? g_k : g_v;

    const int lr = tid >> 1;          // 0..127 row of tile
    const int lc = (tid & 1) * 16;    // 0 or 16 col offset

    float acc[2][8][4];
#pragma unroll
    for (int i = 0; i < 2; i++)
#pragma unroll
        for (int j = 0; j < 8; j++)
#pragma unroll
            for (int c = 0; c < 4; c++) acc[i][j][c] = 0.f;

    const float* xrow = x + (size_t)(mb + lr) * 512 + lc;
    const float* wrow = W + (size_t)(nw0 + lr) * 512 + lc;

    for (int k0 = 0; k0 < 512; k0 += 32) {
#pragma unroll
        for (int i = 0; i < 4; i++) {
            float4 va = *(const float4*)(xrow + k0 + i * 4);
            float4 vb = *(const float4*)(wrow + k0 + i * 4);
            uint4 ua = make_uint4(f2tf(va.x), f2tf(va.y), f2tf(va.z), f2tf(va.w));
            uint4 ub = make_uint4(f2tf(vb.x), f2tf(vb.y), f2tf(vb.z), f2tf(vb.w));
            *(uint4*)&As[lr][lc + i * 4] = ua;
            *(uint4*)&Bs[lr][lc + i * 4] = ub;
        }
        __syncthreads();

#pragma unroll
        for (int k8 = 0; k8 < 4; k8++) {
            uint32_t a[2][4];
#pragma unroll
            for (int i = 0; i < 2; i++) {
                a[i][0] = As[wm + i * 16 + g    ][k8 * 8 + tig];
                a[i][1] = As[wm + i * 16 + g + 8][k8 * 8 + tig];
                a[i][2] = As[wm + i * 16 + g    ][k8 * 8 + tig + 4];
                a[i][3] = As[wm + i * 16 + g + 8][k8 * 8 + tig + 4];
            }
#pragma unroll
            for (int j = 0; j < 8; j++) {
                uint32_t b[2];
                b[0] = Bs[wn + j * 8 + g][k8 * 8 + tig];
                b[1] = Bs[wn + j * 8 + g][k8 * 8 + tig + 4];
                mma_tf32(acc[0][j], a[0], b);
                mma_tf32(acc[1][j], a[1], b);
            }
        }
        __syncthreads();
    }

    // Epilogue: scatter into [bw][h][t][d]; c0/c1 are adjacent d -> 8B stores, full sectors per quad.
#pragma unroll
    for (int i = 0; i < 2; i++) {
        const int m0 = mb + wm + i * 16 + g;
#pragma unroll
        for (int j = 0; j < 8; j++) {
            const int n = nw0 + wn + j * 8 + tig * 2;
            const float bv0 = bias[n], bv1 = bias[n + 1];
            const int h = n >> 6, d = n & 63;
            {
                const int m = m0;
                size_t o = (((size_t)(m >> 6) * 8 + h) * 64 + (m & 63)) * 64 + d;
                *(float2*)&dst[o] = make_float2(acc[i][j][0] + bv0, acc[i][j][1] + bv1);
            }
            {
                const int m = m0 + 8;
                size_t o = (((size_t)(m >> 6) * 8 + h) * 64 + (m & 63)) * 64 + d;
                *(float2*)&dst[o] = make_float2(acc[i][j][2] + bv0, acc[i][j][3] + bv1);
            }
        }
    }
}

// ---------------------------------------------------------------------------
// Kernel B: per-(window, head) attention. Grid = 4096 CTAs x 128 threads.
// S = QK^T * scale + bias ; softmax rows ; O = P V. All GEMMs tf32 mma.
// ---------------------------------------------------------------------------
__global__ void __launch_bounds__(128, 1) attn_kernel(
    const float* __restrict__ Bbias, float* __restrict__ out)
{
    extern __shared__ uint32_t smbuf[];
    uint32_t* qp_s = smbuf;              // [64][68] : Q, later overwritten by P (warp-private rows)
    uint32_t* k_s  = smbuf + 64 * 68;    // [t][d]
    uint32_t* v_s  = smbuf + 2 * 64 * 68;// [d][t]  (transposed -> col-major B operand for O-mma)

    const int tid  = threadIdx.x;
    const int warp = tid >> 5, lane = tid & 31;
    const int g = lane >> 2, tig = lane & 3;
    const int wh = blockIdx.x;            // bw*8 + h
    const int h  = wh & 7;
    const int bw = wh >> 3;
    const size_t base = (size_t)wh * 4096;

#pragma unroll 8
    for (int i = 0; i < 32; i++) {
        const int idx = tid + i * 128;    // 0..4095
        const int t = idx >> 6, d = idx & 63;
        qp_s[t * 68 + d] = f2tf(g_q[base + idx]);
        k_s [t * 68 + d] = f2tf(g_k[base + idx]);
        v_s [d * 68 + t] = f2tf(g_v[base + idx]);
    }
    __syncthreads();

    const int qr = warp * 16;             // this warp's 16 query rows

    // ---- S = Q K^T ----
    float s[8][4];
#pragma unroll
    for (int j = 0; j < 8; j++)
#pragma unroll
        for (int c = 0; c < 4; c++) s[j][c] = 0.f;

#pragma unroll
    for (int k8 = 0; k8 < 8; k8++) {
        uint32_t a[4];
        a[0] = qp_s[(qr + g    ) * 68 + k8 * 8 + tig];
        a[1] = qp_s[(qr + g + 8) * 68 + k8 * 8 + tig];
        a[2] = qp_s[(qr + g    ) * 68 + k8 * 8 + tig + 4];
        a[3] = qp_s[(qr + g + 8) * 68 + k8 * 8 + tig + 4];
#pragma unroll
        for (int j = 0; j < 8; j++) {
            uint32_t b[2];
            b[0] = k_s[(j * 8 + g) * 68 + k8 * 8 + tig];
            b[1] = k_s[(j * 8 + g) * 68 + k8 * 8 + tig + 4];
            mma_tf32(s[j], a, b);
        }
    }

    // ---- scale + bias + softmax (rows qr+g and qr+g+8; quad owns a row) ----
    const float scale = 0.125f;  // 1/sqrt(64)
    float mx0 = -1e30f, mx1 = -1e30f;
#pragma unroll
    for (int j = 0; j < 8; j++) {
        float2 b0 = *(const float2*)&Bbias[(qr + g    ) * 64 + j * 8 + tig * 2];
        float2 b1 = *(const float2*)&Bbias[(qr + g + 8) * 64 + j * 8 + tig * 2];
        s[j][0] = s[j][0] * scale + b0.x;
        s[j][1] = s[j][1] * scale + b0.y;
        s[j][2] = s[j][2] * scale + b1.x;
        s[j][3] = s[j][3] * scale + b1.y;
        mx0 = fmaxf(mx0, fmaxf(s[j][0], s[j][1]));
        mx1 = fmaxf(mx1, fmaxf(s[j][2], s[j][3]));
    }
    mx0 = fmaxf(mx0, __shfl_xor_sync(0xffffffffu, mx0, 1));
    mx0 = fmaxf(mx0, __shfl_xor_sync(0xffffffffu, mx0, 2));
    mx1 = fmaxf(mx1, __shfl_xor_sync(0xffffffffu, mx1, 1));
    mx1 = fmaxf(mx1, __shfl_xor_sync(0xffffffffu, mx1, 2));

    float sum0 = 0.f, sum1 = 0.f;
#pragma unroll
    for (int j = 0; j < 8; j++) {
        s[j][0] = __expf(s[j][0] - mx0);
        s[j][1] = __expf(s[j][1] - mx0);
        s[j][2] = __expf(s[j][2] - mx1);
        s[j][3] = __expf(s[j][3] - mx1);
        sum0 += s[j][0] + s[j][1];
        sum1 += s[j][2] + s[j][3];
    }
    sum0 += __shfl_xor_sync(0xffffffffu, sum0, 1);
    sum0 += __shfl_xor_sync(0xffffffffu, sum0, 2);
    sum1 += __shfl_xor_sync(0xffffffffu, sum1, 1);
    sum1 += __shfl_xor_sync(0xffffffffu, sum1, 2);
    const float inv0 = 1.0f / sum0, inv1 = 1.0f / sum1;

    // ---- write P over Q's smem (this warp reads only its own 16 rows) ----
    __syncwarp();
#pragma unroll
    for (int j = 0; j < 8; j++) {
        qp_s[(qr + g    ) * 68 + j * 8 + tig * 2    ] = f2tf(s[j][0] * inv0);
        qp_s[(qr + g    ) * 68 + j * 8 + tig * 2 + 1] = f2tf(s[j][1] * inv0);
        qp_s[(qr + g + 8) * 68 + j * 8 + tig * 2    ] = f2tf(s[j][2] * inv1);
        qp_s[(qr + g + 8) * 68 + j * 8 + tig * 2 + 1] = f2tf(s[j][3] * inv1);
    }
    __syncwarp();

    // ---- O = P V ----
    float o[8][4];
#pragma unroll
    for (int j = 0; j < 8; j++)
#pragma unroll
        for (int c = 0; c < 4; c++) o[j][c] = 0.f;

#pragma unroll
    for (int k8 = 0; k8 < 8; k8++) {
        uint32_t a[4];
        a[0] = qp_s[(qr + g    ) * 68 + k8 * 8 + tig];
        a[1] = qp_s[(qr + g + 8) * 68 + k8 * 8 + tig];
        a[2] = qp_s[(qr + g    ) * 68 + k8 * 8 + tig + 4];
        a[3] = qp_s[(qr + g + 8) * 68 + k8 * 8 + tig + 4];
#pragma unroll
        for (int j = 0; j < 8; j++) {
            uint32_t b[2];
            b[0] = v_s[(j * 8 + g) * 68 + k8 * 8 + tig];      // v_s[d][t] == B col-major (kt, d)
            b[1] = v_s[(j * 8 + g) * 68 + k8 * 8 + tig + 4];
            mma_tf32(o[j], a, b);
        }
    }

    // ---- write output: flat[((bw*64 + t) * 512) + h*64 + d] ----
    float* o0 = out + ((size_t)bw * 64 + qr + g) * 512 + h * 64;
    float* o1 = o0 + 8 * 512;
#pragma unroll
    for (int j = 0; j < 8; j++) {
        *(float2*)&o0[j * 8 + tig * 2] = make_float2(o[j][0], o[j][1]);
        *(float2*)&o1[j * 8 + tig * 2] = make_float2(o[j][2], o[j][3]);
    }
}

// ---------------------------------------------------------------------------
extern "C" void kernel_launch(void* const* d_in, const int* in_sizes, int n_in,
                              void* d_out, int out_size)
{
    const float* x  = (const float*)d_in[0];
    const float* Wq = (const float*)d_in[1];
    const float* bq = (const float*)d_in[2];
    const float* Wk = (const float*)d_in[3];
    const float* bk = (const float*)d_in[4];
    const float* Wv = (const float*)d_in[5];
    const float* bv = (const float*)d_in[6];
    const float* Bb = (const float*)d_in[7];
    float* out = (float*)d_out;

    // Idempotent, non-stream host call (legal under graph capture; no alloc).
    cudaFuncSetAttribute(attn_kernel, cudaFuncAttributeMaxDynamicSharedMemorySize,
                         3 * 64 * 68 * 4);

    dim3 gA(256, 12);  // 256 M-tiles x 12 N-tiles (Q|K|V)
    qkv_proj_kernel<<<gA, 256>>>(x, Wq, bq, Wk, bk, Wv, bv);

    attn_kernel<<<4096, 128, 3 * 64 * 68 * 4>>>(Bb, out);
}

// round 3
// speedup vs baseline: 1.2962x; 1.2962x over previous
#include <cuda_runtime.h>
#include <cstdint>

// Scratch: Q,K,V in per-(window,head) layout [bw][h][t][d], 512*8*64*64 floats each (64MB).
__device__ float g_q[512 * 8 * 64 * 64];
__device__ float g_k[512 * 8 * 64 * 64];
__device__ float g_v[512 * 8 * 64 * 64];

__device__ __forceinline__ uint32_t f2tf(float f) {
    uint32_t u;
    asm("cvt.rna.tf32.f32 %0, %1;" : "=r"(u) : "f"(f));
    return u;
}

__device__ __forceinline__ void mma_tf32(float c[4], const uint32_t a[4], const uint32_t b[2]) {
    asm volatile(
        "mma.sync.aligned.m16n8k8.row.col.f32.tf32.tf32.f32 "
        "{%0,%1,%2,%3}, {%4,%5,%6,%7}, {%8,%9}, {%0,%1,%2,%3};"
        : "+f"(c[0]), "+f"(c[1]), "+f"(c[2]), "+f"(c[3])
        : "r"(a[0]), "r"(a[1]), "r"(a[2]), "r"(a[3]), "r"(b[0]), "r"(b[1]));
}

__device__ __forceinline__ void cp_async16(uint32_t smem_addr, const void* gptr) {
    asm volatile("cp.async.cg.shared.global [%0], [%1], 16;\n"
                 :: "r"(smem_addr), "l"(gptr));
}
__device__ __forceinline__ void cp_commit() {
    asm volatile("cp.async.commit_group;");
}
template <int N>
__device__ __forceinline__ void cp_wait() {
    asm volatile("cp.async.wait_group %0;" :: "n"(N));
}

// ---------------------------------------------------------------------------
// Kernel A: QKV projection. y[m, n] = sum_k x[m,k] * W[n,k] + b[n]
// M = 32768, N = 1536 (Q|K|V), K = 512.
// CTA tile 128x128, 128 threads (4 warps, 64x64 warp tiles).
// 4-stage cp.async pipeline, K-chunk 16, prefetch distance 3.
// Epilogue scatters into g_q/g_k/g_v as [bw][h][t][d].
// ---------------------------------------------------------------------------
#define STAGES 4
#define KC 16
#define PITCH 20                         // 16 + 4 pad -> conflict-free frags
#define STAGE_ELEMS (2 * 128 * PITCH)    // A + B per stage (floats)

__global__ void __launch_bounds__(128) qkv_proj_kernel(
    const float* __restrict__ x,
    const float* __restrict__ Wq, const float* __restrict__ bq,
    const float* __restrict__ Wk, const float* __restrict__ bk,
    const float* __restrict__ Wv, const float* __restrict__ bv)
{
    extern __shared__ float sm[];

    const int tid  = threadIdx.x;
    const int warp = tid >> 5, lane = tid & 31;
    const int g = lane >> 2, tig = lane & 3;
    const int wm = (warp >> 1) * 64;  // warp row offset (64x64 warp tile)
    const int wn = (warp & 1) * 64;

    const int mb = blockIdx.x * 128;
    const int nb = blockIdx.y * 128;
    const int which = nb >> 9;            // 0=Q, 1=K, 2=V
    const int nw0 = nb & 511;
    const float* __restrict__ W    = (which == 0) ? Wq : (which == 1) ? Wk : Wv;
    const float* __restrict__ bias = (which == 0) ? bq : (which == 1) ? bk : bv;
    float* __restrict__ dst        = (which == 0) ? g_q : (which == 1) ? g_k : g_v;

    // Per-thread copy geometry: 512 16B-chunks per matrix per stage, 4/thread.
    // chunk c: row = c>>2, col = (c&3)*4
    const uint32_t smem_base = (uint32_t)__cvta_generic_to_shared(sm);

    float acc[4][8][4];
#pragma unroll
    for (int i = 0; i < 4; i++)
#pragma unroll
        for (int j = 0; j < 8; j++)
#pragma unroll
            for (int c = 0; c < 4; c++) acc[i][j][c] = 0.f;

    auto issue_copy = [&](int s, int kc) {
        const uint32_t sA = smem_base + (uint32_t)(s * STAGE_ELEMS) * 4u;
        const uint32_t sB = sA + 128u * PITCH * 4u;
        const int k0 = kc * KC;
#pragma unroll
        for (int i = 0; i < 4; i++) {
            const int c = i * 128 + tid;
            const int row = c >> 2;
            const int col = (c & 3) * 4;
            cp_async16(sA + (uint32_t)(row * PITCH + col) * 4u,
                       x + (size_t)(mb + row) * 512 + k0 + col);
            cp_async16(sB + (uint32_t)(row * PITCH + col) * 4u,
                       W + (size_t)(nw0 + row) * 512 + k0 + col);
        }
        cp_commit();
    };

    // Prologue: prefetch 3 stages
    issue_copy(0, 0);
    issue_copy(1, 1);
    issue_copy(2, 2);

    for (int kc = 0; kc < 32; kc++) {
        if (kc < 29) cp_wait<2>(); else cp_wait<0>();
        __syncthreads();
        if (kc + 3 < 32) issue_copy((kc + 3) & 3, kc + 3);

        const float* A = sm + (kc & 3) * STAGE_ELEMS;
        const float* B = A + 128 * PITCH;

#pragma unroll
        for (int k8 = 0; k8 < 2; k8++) {
            uint32_t a[4][4];
#pragma unroll
            for (int i = 0; i < 4; i++) {
                const int r0 = (wm + i * 16 + g) * PITCH + k8 * 8 + tig;
                a[i][0] = f2tf(A[r0]);
                a[i][1] = f2tf(A[r0 + 8 * PITCH]);
                a[i][2] = f2tf(A[r0 + 4]);
                a[i][3] = f2tf(A[r0 + 8 * PITCH + 4]);
            }
#pragma unroll
            for (int j = 0; j < 8; j++) {
                const int rb = (wn + j * 8 + g) * PITCH + k8 * 8 + tig;
                uint32_t b[2];
                b[0] = f2tf(B[rb]);
                b[1] = f2tf(B[rb + 4]);
#pragma unroll
                for (int i = 0; i < 4; i++) mma_tf32(acc[i][j], a[i], b);
            }
        }
    }

    // Epilogue: scatter into [bw][h][t][d]; adjacent d pairs -> 8B stores.
#pragma unroll
    for (int i = 0; i < 4; i++) {
        const int m0 = mb + wm + i * 16 + g;
#pragma unroll
        for (int j = 0; j < 8; j++) {
            const int n = nw0 + wn + j * 8 + tig * 2;
            const float bv0 = bias[n], bv1 = bias[n + 1];
            const int h = n >> 6, d = n & 63;
            {
                const int m = m0;
                size_t o = (((size_t)(m >> 6) * 8 + h) * 64 + (m & 63)) * 64 + d;
                *(float2*)&dst[o] = make_float2(acc[i][j][0] + bv0, acc[i][j][1] + bv1);
            }
            {
                const int m = m0 + 8;
                size_t o = (((size_t)(m >> 6) * 8 + h) * 64 + (m & 63)) * 64 + d;
                *(float2*)&dst[o] = make_float2(acc[i][j][2] + bv0, acc[i][j][3] + bv1);
            }
        }
    }
}

// ---------------------------------------------------------------------------
// Kernel B: per-(window, head) attention. Grid = 4096 CTAs x 128 threads.
// S = QK^T * scale + bias ; softmax rows ; O = P V. All GEMMs tf32 mma.
// ---------------------------------------------------------------------------
__global__ void __launch_bounds__(128, 1) attn_kernel(
    const float* __restrict__ Bbias, float* __restrict__ out)
{
    extern __shared__ uint32_t smbuf[];
    uint32_t* qp_s = smbuf;              // [64][68] : Q, later overwritten by P (warp-private rows)
    uint32_t* k_s  = smbuf + 64 * 68;    // [t][d]
    uint32_t* v_s  = smbuf + 2 * 64 * 68;// [d][t]  (transposed -> col-major B operand for O-mma)

    const int tid  = threadIdx.x;
    const int warp = tid >> 5, lane = tid & 31;
    const int g = lane >> 2, tig = lane & 3;
    const int wh = blockIdx.x;            // bw*8 + h
    const int h  = wh & 7;
    const int bw = wh >> 3;
    const size_t base = (size_t)wh * 4096;

#pragma unroll 8
    for (int i = 0; i < 32; i++) {
        const int idx = tid + i * 128;    // 0..4095
        const int t = idx >> 6, d = idx & 63;
        qp_s[t * 68 + d] = f2tf(g_q[base + idx]);
        k_s [t * 68 + d] = f2tf(g_k[base + idx]);
        v_s [d * 68 + t] = f2tf(g_v[base + idx]);
    }
    __syncthreads();

    const int qr = warp * 16;             // this warp's 16 query rows

    // ---- S = Q K^T ----
    float s[8][4];
#pragma unroll
    for (int j = 0; j < 8; j++)
#pragma unroll
        for (int c = 0; c < 4; c++) s[j][c] = 0.f;

#pragma unroll
    for (int k8 = 0; k8 < 8; k8++) {
        uint32_t a[4];
        a[0] = qp_s[(qr + g    ) * 68 + k8 * 8 + tig];
        a[1] = qp_s[(qr + g + 8) * 68 + k8 * 8 + tig];
        a[2] = qp_s[(qr + g    ) * 68 + k8 * 8 + tig + 4];
        a[3] = qp_s[(qr + g + 8) * 68 + k8 * 8 + tig + 4];
#pragma unroll
        for (int j = 0; j < 8; j++) {
            uint32_t b[2];
            b[0] = k_s[(j * 8 + g) * 68 + k8 * 8 + tig];
            b[1] = k_s[(j * 8 + g) * 68 + k8 * 8 + tig + 4];
            mma_tf32(s[j], a, b);
        }
    }

    // ---- scale + bias + softmax (rows qr+g and qr+g+8; quad owns a row) ----
    const float scale = 0.125f;  // 1/sqrt(64)
    float mx0 = -1e30f, mx1 = -1e30f;
#pragma unroll
    for (int j = 0; j < 8; j++) {
        float2 b0 = *(const float2*)&Bbias[(qr + g    ) * 64 + j * 8 + tig * 2];
        float2 b1 = *(const float2*)&Bbias[(qr + g + 8) * 64 + j * 8 + tig * 2];
        s[j][0] = s[j][0] * scale + b0.x;
        s[j][1] = s[j][1] * scale + b0.y;
        s[j][2] = s[j][2] * scale + b1.x;
        s[j][3] = s[j][3] * scale + b1.y;
        mx0 = fmaxf(mx0, fmaxf(s[j][0], s[j][1]));
        mx1 = fmaxf(mx1, fmaxf(s[j][2], s[j][3]));
    }
    mx0 = fmaxf(mx0, __shfl_xor_sync(0xffffffffu, mx0, 1));
    mx0 = fmaxf(mx0, __shfl_xor_sync(0xffffffffu, mx0, 2));
    mx1 = fmaxf(mx1, __shfl_xor_sync(0xffffffffu, mx1, 1));
    mx1 = fmaxf(mx1, __shfl_xor_sync(0xffffffffu, mx1, 2));

    float sum0 = 0.f, sum1 = 0.f;
#pragma unroll
    for (int j = 0; j < 8; j++) {
        s[j][0] = __expf(s[j][0] - mx0);
        s[j][1] = __expf(s[j][1] - mx0);
        s[j][2] = __expf(s[j][2] - mx1);
        s[j][3] = __expf(s[j][3] - mx1);
        sum0 += s[j][0] + s[j][1];
        sum1 += s[j][2] + s[j][3];
    }
    sum0 += __shfl_xor_sync(0xffffffffu, sum0, 1);
    sum0 += __shfl_xor_sync(0xffffffffu, sum0, 2);
    sum1 += __shfl_xor_sync(0xffffffffu, sum1, 1);
    sum1 += __shfl_xor_sync(0xffffffffu, sum1, 2);
    const float inv0 = 1.0f / sum0, inv1 = 1.0f / sum1;

    // ---- write P over Q's smem (this warp reads only its own 16 rows) ----
    __syncwarp();
#pragma unroll
    for (int j = 0; j < 8; j++) {
        qp_s[(qr + g    ) * 68 + j * 8 + tig * 2    ] = f2tf(s[j][0] * inv0);
        qp_s[(qr + g    ) * 68 + j * 8 + tig * 2 + 1] = f2tf(s[j][1] * inv0);
        qp_s[(qr + g + 8) * 68 + j * 8 + tig * 2    ] = f2tf(s[j][2] * inv1);
        qp_s[(qr + g + 8) * 68 + j * 8 + tig * 2 + 1] = f2tf(s[j][3] * inv1);
    }
    __syncwarp();

    // ---- O = P V ----
    float o[8][4];
#pragma unroll
    for (int j = 0; j < 8; j++)
#pragma unroll
        for (int c = 0; c < 4; c++) o[j][c] = 0.f;

#pragma unroll
    for (int k8 = 0; k8 < 8; k8++) {
        uint32_t a[4];
        a[0] = qp_s[(qr + g    ) * 68 + k8 * 8 + tig];
        a[1] = qp_s[(qr + g + 8) * 68 + k8 * 8 + tig];
        a[2] = qp_s[(qr + g    ) * 68 + k8 * 8 + tig + 4];
        a[3] = qp_s[(qr + g + 8) * 68 + k8 * 8 + tig + 4];
#pragma unroll
        for (int j = 0; j < 8; j++) {
            uint32_t b[2];
            b[0] = v_s[(j * 8 + g) * 68 + k8 * 8 + tig];      // v_s[d][t] == B col-major (kt, d)
            b[1] = v_s[(j * 8 + g) * 68 + k8 * 8 + tig + 4];
            mma_tf32(o[j], a, b);
        }
    }

    // ---- write output: flat[((bw*64 + t) * 512) + h*64 + d] ----
    float* o0 = out + ((size_t)bw * 64 + qr + g) * 512 + h * 64;
    float* o1 = o0 + 8 * 512;
#pragma unroll
    for (int j = 0; j < 8; j++) {
        *(float2*)&o0[j * 8 + tig * 2] = make_float2(o[j][0], o[j][1]);
        *(float2*)&o1[j * 8 + tig * 2] = make_float2(o[j][2], o[j][3]);
    }
}

// ---------------------------------------------------------------------------
extern "C" void kernel_launch(void* const* d_in, const int* in_sizes, int n_in,
                              void* d_out, int out_size)
{
    const float* x  = (const float*)d_in[0];
    const float* Wq = (const float*)d_in[1];
    const float* bq = (const float*)d_in[2];
    const float* Wk = (const float*)d_in[3];
    const float* bk = (const float*)d_in[4];
    const float* Wv = (const float*)d_in[5];
    const float* bv = (const float*)d_in[6];
    const float* Bb = (const float*)d_in[7];
    float* out = (float*)d_out;

    // Idempotent, non-stream host calls (legal under graph capture; no alloc).
    cudaFuncSetAttribute(qkv_proj_kernel, cudaFuncAttributeMaxDynamicSharedMemorySize,
                         STAGES * STAGE_ELEMS * 4);
    cudaFuncSetAttribute(attn_kernel, cudaFuncAttributeMaxDynamicSharedMemorySize,
                         3 * 64 * 68 * 4);

    dim3 gA(256, 12);  // 256 M-tiles x 12 N-tiles (Q|K|V)
    qkv_proj_kernel<<<gA, 128, STAGES * STAGE_ELEMS * 4>>>(x, Wq, bq, Wk, bk, Wv, bv);

    attn_kernel<<<4096, 128, 3 * 64 * 68 * 4>>>(Bb, out);
}

// round 4
// speedup vs baseline: 1.3718x; 1.0583x over previous
#include <cuda_runtime.h>
#include <cstdint>

// Scratch buffers (device globals; no runtime allocation).
__device__ __align__(16) uint32_t g_qkv[3 * 512 * 8 * 64 * 64];  // tf32 bits, [which][bw][h][t][d]
__device__ __align__(16) uint32_t g_xtf[32768 * 512];            // x pre-converted to tf32 bits
__device__ __align__(16) uint32_t g_wtf[1536 * 512];             // Wq|Wk|Wv pre-converted

__device__ __forceinline__ uint32_t f2tf(float f) {
    uint32_t u;
    asm("cvt.rna.tf32.f32 %0, %1;" : "=r"(u) : "f"(f));
    return u;
}

__device__ __forceinline__ void mma_tf32(float c[4], const uint32_t a[4], const uint32_t b[2]) {
    asm volatile(
        "mma.sync.aligned.m16n8k8.row.col.f32.tf32.tf32.f32 "
        "{%0,%1,%2,%3}, {%4,%5,%6,%7}, {%8,%9}, {%0,%1,%2,%3};"
        : "+f"(c[0]), "+f"(c[1]), "+f"(c[2]), "+f"(c[3])
        : "r"(a[0]), "r"(a[1]), "r"(a[2]), "r"(a[3]), "r"(b[0]), "r"(b[1]));
}

__device__ __forceinline__ void cp_async16(uint32_t smem_addr, const void* gptr) {
    asm volatile("cp.async.cg.shared.global [%0], [%1], 16;\n"
                 :: "r"(smem_addr), "l"(gptr));
}
__device__ __forceinline__ void cp_commit() {
    asm volatile("cp.async.commit_group;");
}
template <int N>
__device__ __forceinline__ void cp_wait() {
    asm volatile("cp.async.wait_group %0;" :: "n"(N));
}

// ---------------------------------------------------------------------------
// Pre-convert kernels: fp32 -> tf32(RN) bits, vectorized 16B.
// ---------------------------------------------------------------------------
__global__ void __launch_bounds__(256) conv_x_kernel(const float* __restrict__ x)
{
    const int i = blockIdx.x * 256 + threadIdx.x;      // 4,194,304 uint4s
    float4 v = ((const float4*)x)[i];
    uint4 u = make_uint4(f2tf(v.x), f2tf(v.y), f2tf(v.z), f2tf(v.w));
    ((uint4*)g_xtf)[i] = u;
}

__global__ void __launch_bounds__(256) conv_w_kernel(
    const float* __restrict__ Wq, const float* __restrict__ Wk, const float* __restrict__ Wv)
{
    const int i = blockIdx.x * 256 + threadIdx.x;      // 196,608 uint4s (65536 per matrix)
    const int which = i >> 16;
    const int sub = i & 65535;
    const float* W = (which == 0) ? Wq : (which == 1) ? Wk : Wv;
    float4 v = ((const float4*)W)[sub];
    uint4 u = make_uint4(f2tf(v.x), f2tf(v.y), f2tf(v.z), f2tf(v.w));
    ((uint4*)g_wtf)[i] = u;
}

// ---------------------------------------------------------------------------
// Kernel A: QKV projection. y[m,n] = sum_k x[m,k]*W[n,k] + b[n]
// M=32768, N=1536, K=512. CTA tile 256x128, 256 threads (8 warps, 64x64 warp
// tiles). 4-stage cp.async pipeline (K-chunk 16). Operands pre-converted ->
// no CVT in mainloop. Epilogue adds bias, converts to tf32 bits, scatters
// into g_qkv as [which][bw][h][t][d].
// Grid: (12, 128) with blockIdx.x = N-tile -> x rows reused across N via L2.
// ---------------------------------------------------------------------------
#define STAGES 4
#define KC 16
#define PITCH 20                                // 16 + 4 pad
#define A_STAGE (256 * PITCH)                   // words
#define B_STAGE (128 * PITCH)
#define STAGE_ELEMS (A_STAGE + B_STAGE)

__global__ void __launch_bounds__(256) qkv_proj_kernel(
    const float* __restrict__ bq, const float* __restrict__ bk, const float* __restrict__ bv)
{
    extern __shared__ uint32_t sm[];

    const int tid  = threadIdx.x;
    const int warp = tid >> 5, lane = tid & 31;
    const int g = lane >> 2, tig = lane & 3;
    const int wm = (warp >> 1) * 64;
    const int wn = (warp & 1) * 64;

    const int nb = blockIdx.x * 128;            // 0..1408
    const int mb = blockIdx.y * 256;
    const int which = nb >> 9;
    const int nw0 = nb & 511;
    const float* __restrict__ bias = (which == 0) ? bq : (which == 1) ? bk : bv;
    uint32_t* __restrict__ dst = g_qkv + (size_t)which * (512u * 8u * 64u * 64u);

    const uint32_t smem_base = (uint32_t)__cvta_generic_to_shared(sm);

    float acc[4][8][4];
#pragma unroll
    for (int i = 0; i < 4; i++)
#pragma unroll
        for (int j = 0; j < 8; j++)
#pragma unroll
            for (int c = 0; c < 4; c++) acc[i][j][c] = 0.f;

    // Per stage: A = 256 rows x 4 chunks = 1024 chunks, B = 512 chunks; 6/thread.
    auto issue_copy = [&](int s, int kc) {
        const uint32_t sA = smem_base + (uint32_t)(s * STAGE_ELEMS) * 4u;
        const uint32_t sB = sA + (uint32_t)A_STAGE * 4u;
        const int k0 = kc * KC;
#pragma unroll
        for (int i = 0; i < 6; i++) {
            const int c = i * 256 + tid;        // 0..1535
            if (c < 1024) {
                const int row = c >> 2;
                const int col = (c & 3) * 4;
                cp_async16(sA + (uint32_t)(row * PITCH + col) * 4u,
                           g_xtf + (size_t)(mb + row) * 512 + k0 + col);
            } else {
                const int cb = c - 1024;
                const int row = cb >> 2;
                const int col = (cb & 3) * 4;
                cp_async16(sB + (uint32_t)(row * PITCH + col) * 4u,
                           g_wtf + (size_t)(nb + row) * 512 + k0 + col);
            }
        }
        cp_commit();
    };

    issue_copy(0, 0);
    issue_copy(1, 1);
    issue_copy(2, 2);

    for (int kc = 0; kc < 32; kc++) {
        if (kc < 29) cp_wait<2>(); else cp_wait<0>();
        __syncthreads();
        if (kc + 3 < 32) issue_copy((kc + 3) & 3, kc + 3);

        const uint32_t* A = sm + (kc & 3) * STAGE_ELEMS;
        const uint32_t* B = A + A_STAGE;

#pragma unroll
        for (int k8 = 0; k8 < 2; k8++) {
            uint32_t a[4][4];
#pragma unroll
            for (int i = 0; i < 4; i++) {
                const int r0 = (wm + i * 16 + g) * PITCH + k8 * 8 + tig;
                a[i][0] = A[r0];
                a[i][1] = A[r0 + 8 * PITCH];
                a[i][2] = A[r0 + 4];
                a[i][3] = A[r0 + 8 * PITCH + 4];
            }
#pragma unroll
            for (int j = 0; j < 8; j++) {
                const int rb = (wn + j * 8 + g) * PITCH + k8 * 8 + tig;
                uint32_t b[2];
                b[0] = B[rb];
                b[1] = B[rb + 4];
#pragma unroll
                for (int i = 0; i < 4; i++) mma_tf32(acc[i][j], a[i], b);
            }
        }
    }

    // Epilogue: bias add (fp32), convert to tf32 bits, scatter [bw][h][t][d].
#pragma unroll
    for (int i = 0; i < 4; i++) {
        const int m0 = mb + wm + i * 16 + g;
#pragma unroll
        for (int j = 0; j < 8; j++) {
            const int col = nw0 + wn + j * 8 + tig * 2;   // within this matrix
            const float bv0 = bias[col], bv1 = bias[col + 1];
            const int h = col >> 6, d = col & 63;
            {
                const int m = m0;
                size_t o = (((size_t)(m >> 6) * 8 + h) * 64 + (m & 63)) * 64 + d;
                *(uint2*)&dst[o] = make_uint2(f2tf(acc[i][j][0] + bv0), f2tf(acc[i][j][1] + bv1));
            }
            {
                const int m = m0 + 8;
                size_t o = (((size_t)(m >> 6) * 8 + h) * 64 + (m & 63)) * 64 + d;
                *(uint2*)&dst[o] = make_uint2(f2tf(acc[i][j][2] + bv0), f2tf(acc[i][j][3] + bv1));
            }
        }
    }
}

// ---------------------------------------------------------------------------
// Kernel B: per-(window, head) attention. 4096 CTAs x 128 threads.
// Inputs already tf32 bits -> uint4 loads, no conversion.
// ---------------------------------------------------------------------------
__global__ void __launch_bounds__(128, 1) attn_kernel(
    const float* __restrict__ Bbias, float* __restrict__ out)
{
    extern __shared__ uint32_t smbuf[];
    uint32_t* qp_s = smbuf;               // [64][68] Q, later P (warp-private rows)
    uint32_t* k_s  = smbuf + 64 * 68;     // [t][d]
    uint32_t* v_s  = smbuf + 2 * 64 * 68; // [d][t]

    const int tid  = threadIdx.x;
    const int warp = tid >> 5, lane = tid & 31;
    const int g = lane >> 2, tig = lane & 3;
    const int wh = blockIdx.x;
    const int h  = wh & 7;
    const int bw = wh >> 3;
    const size_t base = (size_t)wh * 4096;

    const uint4* q4 = (const uint4*)(g_qkv + base);
    const uint4* k4 = (const uint4*)(g_qkv + 512u * 8u * 64u * 64u + base);
    const uint4* v4 = (const uint4*)(g_qkv + 2u * 512u * 8u * 64u * 64u + base);

#pragma unroll
    for (int i = 0; i < 8; i++) {
        const int c = i * 128 + tid;      // 0..1023 chunks of 16B
        const int t = c >> 4, d4 = (c & 15) * 4;
        uint4 q = q4[c];
        uint4 k = k4[c];
        uint4 v = v4[c];
        *(uint4*)&qp_s[t * 68 + d4] = q;
        *(uint4*)&k_s [t * 68 + d4] = k;
        v_s[(d4    ) * 68 + t] = v.x;     // transpose for O-mma B operand
        v_s[(d4 + 1) * 68 + t] = v.y;
        v_s[(d4 + 2) * 68 + t] = v.z;
        v_s[(d4 + 3) * 68 + t] = v.w;
    }
    __syncthreads();

    const int qr = warp * 16;

    // ---- S = Q K^T ----
    float s[8][4];
#pragma unroll
    for (int j = 0; j < 8; j++)
#pragma unroll
        for (int c = 0; c < 4; c++) s[j][c] = 0.f;

#pragma unroll
    for (int k8 = 0; k8 < 8; k8++) {
        uint32_t a[4];
        a[0] = qp_s[(qr + g    ) * 68 + k8 * 8 + tig];
        a[1] = qp_s[(qr + g + 8) * 68 + k8 * 8 + tig];
        a[2] = qp_s[(qr + g    ) * 68 + k8 * 8 + tig + 4];
        a[3] = qp_s[(qr + g + 8) * 68 + k8 * 8 + tig + 4];
#pragma unroll
        for (int j = 0; j < 8; j++) {
            uint32_t b[2];
            b[0] = k_s[(j * 8 + g) * 68 + k8 * 8 + tig];
            b[1] = k_s[(j * 8 + g) * 68 + k8 * 8 + tig + 4];
            mma_tf32(s[j], a, b);
        }
    }

    // ---- scale + bias + softmax ----
    const float scale = 0.125f;
    float mx0 = -1e30f, mx1 = -1e30f;
#pragma unroll
    for (int j = 0; j < 8; j++) {
        float2 b0 = *(const float2*)&Bbias[(qr + g    ) * 64 + j * 8 + tig * 2];
        float2 b1 = *(const float2*)&Bbias[(qr + g + 8) * 64 + j * 8 + tig * 2];
        s[j][0] = s[j][0] * scale + b0.x;
        s[j][1] = s[j][1] * scale + b0.y;
        s[j][2] = s[j][2] * scale + b1.x;
        s[j][3] = s[j][3] * scale + b1.y;
        mx0 = fmaxf(mx0, fmaxf(s[j][0], s[j][1]));
        mx1 = fmaxf(mx1, fmaxf(s[j][2], s[j][3]));
    }
    mx0 = fmaxf(mx0, __shfl_xor_sync(0xffffffffu, mx0, 1));
    mx0 = fmaxf(mx0, __shfl_xor_sync(0xffffffffu, mx0, 2));
    mx1 = fmaxf(mx1, __shfl_xor_sync(0xffffffffu, mx1, 1));
    mx1 = fmaxf(mx1, __shfl_xor_sync(0xffffffffu, mx1, 2));

    float sum0 = 0.f, sum1 = 0.f;
#pragma unroll
    for (int j = 0; j < 8; j++) {
        s[j][0] = __expf(s[j][0] - mx0);
        s[j][1] = __expf(s[j][1] - mx0);
        s[j][2] = __expf(s[j][2] - mx1);
        s[j][3] = __expf(s[j][3] - mx1);
        sum0 += s[j][0] + s[j][1];
        sum1 += s[j][2] + s[j][3];
    }
    sum0 += __shfl_xor_sync(0xffffffffu, sum0, 1);
    sum0 += __shfl_xor_sync(0xffffffffu, sum0, 2);
    sum1 += __shfl_xor_sync(0xffffffffu, sum1, 1);
    sum1 += __shfl_xor_sync(0xffffffffu, sum1, 2);
    const float inv0 = 1.0f / sum0, inv1 = 1.0f / sum1;

    // ---- write P over Q smem (warp-private rows) ----
    __syncwarp();
#pragma unroll
    for (int j = 0; j < 8; j++) {
        qp_s[(qr + g    ) * 68 + j * 8 + tig * 2    ] = f2tf(s[j][0] * inv0);
        qp_s[(qr + g    ) * 68 + j * 8 + tig * 2 + 1] = f2tf(s[j][1] * inv0);
        qp_s[(qr + g + 8) * 68 + j * 8 + tig * 2    ] = f2tf(s[j][2] * inv1);
        qp_s[(qr + g + 8) * 68 + j * 8 + tig * 2 + 1] = f2tf(s[j][3] * inv1);
    }
    __syncwarp();

    // ---- O = P V ----
    float o[8][4];
#pragma unroll
    for (int j = 0; j < 8; j++)
#pragma unroll
        for (int c = 0; c < 4; c++) o[j][c] = 0.f;

#pragma unroll
    for (int k8 = 0; k8 < 8; k8++) {
        uint32_t a[4];
        a[0] = qp_s[(qr + g    ) * 68 + k8 * 8 + tig];
        a[1] = qp_s[(qr + g + 8) * 68 + k8 * 8 + tig];
        a[2] = qp_s[(qr + g    ) * 68 + k8 * 8 + tig + 4];
        a[3] = qp_s[(qr + g + 8) * 68 + k8 * 8 + tig + 4];
#pragma unroll
        for (int j = 0; j < 8; j++) {
            uint32_t b[2];
            b[0] = v_s[(j * 8 + g) * 68 + k8 * 8 + tig];
            b[1] = v_s[(j * 8 + g) * 68 + k8 * 8 + tig + 4];
            mma_tf32(o[j], a, b);
        }
    }

    // ---- output: flat[((bw*64 + t) * 512) + h*64 + d] ----
    float* o0 = out + ((size_t)bw * 64 + qr + g) * 512 + h * 64;
    float* o1 = o0 + 8 * 512;
#pragma unroll
    for (int j = 0; j < 8; j++) {
        *(float2*)&o0[j * 8 + tig * 2] = make_float2(o[j][0], o[j][1]);
        *(float2*)&o1[j * 8 + tig * 2] = make_float2(o[j][2], o[j][3]);
    }
}

// ---------------------------------------------------------------------------
extern "C" void kernel_launch(void* const* d_in, const int* in_sizes, int n_in,
                              void* d_out, int out_size)
{
    const float* x  = (const float*)d_in[0];
    const float* Wq = (const float*)d_in[1];
    const float* bq = (const float*)d_in[2];
    const float* Wk = (const float*)d_in[3];
    const float* bk = (const float*)d_in[4];
    const float* Wv = (const float*)d_in[5];
    const float* bv = (const float*)d_in[6];
    const float* Bb = (const float*)d_in[7];
    float* out = (float*)d_out;

    cudaFuncSetAttribute(qkv_proj_kernel, cudaFuncAttributeMaxDynamicSharedMemorySize,
                         STAGES * STAGE_ELEMS * 4);
    cudaFuncSetAttribute(attn_kernel, cudaFuncAttributeMaxDynamicSharedMemorySize,
                         3 * 64 * 68 * 4);

    conv_x_kernel<<<16384, 256>>>(x);
    conv_w_kernel<<<768, 256>>>(Wq, Wk, Wv);

    dim3 gA(12, 128);   // x = N-tile (fast) -> x L2 reuse across N
    qkv_proj_kernel<<<gA, 256, STAGES * STAGE_ELEMS * 4>>>(bq, bk, bv);

    attn_kernel<<<4096, 128, 3 * 64 * 68 * 4>>>(Bb, out);
}